// round 11
// baseline (speedup 1.0000x reference)
#include <cuda_runtime.h>
#include <cuda_fp16.h>
#include <stdint.h>

#define B 256
#define D 128
#define NCORP 1000000
#define K_TOP 100
#define CAP 4096
#define NBINS 4096
#define FCAP 512
#define TILE_M 128
#define GRID_K1 148
#define TPB_M 38
#define NTILE_MMA (GRID_K1 * TPB_M)        // 5624 tiles
#define MMA_ITEMS (NTILE_MMA * TILE_M)     // 719,872
#define SCAL_START MMA_ITEMS
#define SCAL_CHUNK 1894                    // 148*1894 = 280,312 >= 280,128
#define THR_MULT 3.2f
#define NTHREADS 640

// smem offsets
#define A8_STRIDE 144                   // 128 data bytes + 16 pad
#define A8_BUF    (128 * A8_STRIDE)     // 18,432
#define SM_A      0                     // 2 buffers = 36,864
#define SM_STAGE  36864                 // 65,536 fp32 staging (Q8 at startup)
#define SM_QPK    102400                // 65,536 packed fp16 Q table [k][q]
#define SM_THR    167936                // 1,024
#define SM_TOTAL  168960

// ---------------- scratch (device globals; no allocations) ----------------
__device__ int           g_cnt[B];
__device__ float         g_thrf[B];
__device__ unsigned char g_q8[B * D];       // e4m3 queries (32 KB)
__device__ __half        g_qpk[D * B];      // fp16 Q, [k][q] layout (64 KB)
__device__ int           g_cand_idx[(size_t)B * CAP];
__device__ float         g_cand_score[(size_t)B * CAP];

__device__ __forceinline__ unsigned int fkey(float f) {
    unsigned int u = __float_as_uint(f);
    u ^= (u & 0x80000000u) ? 0xFFFFFFFFu : 0x80000000u;
    return u >> 20;
}
__device__ __forceinline__ void cp_async16(uint32_t saddr, const void* g) {
    asm volatile("cp.async.cg.shared.global [%0], [%1], 16;\n" :: "r"(saddr), "l"(g));
}
__device__ __forceinline__ uint32_t smem_u32(const void* p) {
    uint32_t a;
    asm("{ .reg .u64 t; cvta.to.shared.u64 t, %1; cvt.u32.u64 %0, t; }" : "=r"(a) : "l"(p));
    return a;
}
__device__ __forceinline__ uint32_t pack_e4m3x4(float4 v) {
    uint16_t lo, hi;
    asm("cvt.rn.satfinite.e4m3x2.f32 %0, %1, %2;" : "=h"(lo) : "f"(v.y), "f"(v.x));
    asm("cvt.rn.satfinite.e4m3x2.f32 %0, %1, %2;" : "=h"(hi) : "f"(v.w), "f"(v.z));
    return (uint32_t)lo | ((uint32_t)hi << 16);
}

// ---------------- K0: Q fp32->e4m3 + fp16[k][q] table, thresholds ----------
__global__ __launch_bounds__(256) void qprep_kernel(const float* __restrict__ qry) {
    const int lane = threadIdx.x & 31;
    const int q = blockIdx.x * 8 + (threadIdx.x >> 5);
    float4 v = *(const float4*)(qry + (size_t)q * D + lane * 4);
    *(uint32_t*)&g_q8[(size_t)q * D + lane * 4] = pack_e4m3x4(v);
    g_qpk[(lane * 4 + 0) * B + q] = __float2half_rn(v.x);
    g_qpk[(lane * 4 + 1) * B + q] = __float2half_rn(v.y);
    g_qpk[(lane * 4 + 2) * B + q] = __float2half_rn(v.z);
    g_qpk[(lane * 4 + 3) * B + q] = __float2half_rn(v.w);
    float s = v.x * v.x + v.y * v.y + v.z * v.z + v.w * v.w;
#pragma unroll
    for (int o = 16; o > 0; o >>= 1) s += __shfl_xor_sync(0xFFFFFFFFu, s, o);
    if (lane == 0) {
        g_thrf[q] = THR_MULT * sqrtf(s);
        g_cnt[q] = 0;
    }
}

// ---------------- K1: dual-pipe GEMM + filter --------------------------------
// Warps 0-15: fp8 MMA over 38 tiles (named bar.sync 1,512; single fp32 stage
// with strict per-thread chunk ownership). Warps 16-19: scalar HFMA2 path over
// the corpus tail, running concurrently on the fma pipe.
__device__ __forceinline__ void issue_tile(uint32_t stage, const float* __restrict__ corp,
                                           int tile, int tid) {
    const size_t ib = (size_t)tile * TILE_M;
#pragma unroll
    for (int j = 0; j < 8; j++) {
        int idx = tid + j * 512;          // 0..4095 16B chunks (all items valid)
        int row = idx >> 5;
        int c16 = idx & 31;
        cp_async16(stage + row * 512 + c16 * 16, corp + (ib + row) * D + c16 * 4);
    }
    asm volatile("cp.async.commit_group;\n");
}
__device__ __forceinline__ void convert_chunk(char* sm, int abuf, int j, int tid) {
    int idx = tid + j * 512;              // 0..4095 float4
    int row = idx >> 5;
    int c4  = idx & 31;
    float4 v = ((const float4*)(sm + SM_STAGE))[idx];
    *(uint32_t*)(sm + SM_A + abuf * A8_BUF + row * A8_STRIDE + c4 * 4) = pack_e4m3x4(v);
}
#define MMA_BAR() asm volatile("bar.sync 1, 512;" ::: "memory")

__global__ __launch_bounds__(NTHREADS, 1) void gemm_filter_kernel(const float* __restrict__ corp) {
    extern __shared__ __align__(1024) char sm[];
    const uint32_t sb = smem_u32(sm);
    float* thr = (float*)(sm + SM_THR);

    const int tid  = threadIdx.x;
    const int lane = tid & 31;
    const int wid  = tid >> 5;            // 0..19

    // ---- shared prologue: Q8 -> STAGE, QPK -> SM_QPK, thr ----
    for (int idx = tid; idx < 2048; idx += NTHREADS)
        cp_async16(sb + SM_STAGE + idx * 16, g_q8 + (size_t)idx * 16);
    for (int idx = tid; idx < 4096; idx += NTHREADS)
        cp_async16(sb + SM_QPK + idx * 16, (const char*)g_qpk + (size_t)idx * 16);
    asm volatile("cp.async.commit_group;\n");
    if (tid < B) thr[tid] = g_thrf[tid];
    asm volatile("cp.async.wait_group 0;\n");
    __syncthreads();

    if (wid < 16) {
        // =================== MMA path (warps 0-15) ===================
        const int base = blockIdx.x * TPB_M;

        const int b_l = lane & 15;
        uint32_t bfrag[2][4][2];
#pragma unroll
        for (int nf = 0; nf < 2; nf++) {
#pragma unroll
            for (int ks = 0; ks < 4; ks++) {
                int qrow = wid * 16 + nf * 8 + (b_l & 7);
                uint32_t addr = sb + SM_STAGE + qrow * 128 + ks * 32 + ((b_l >> 3) & 1) * 16;
                asm volatile("ldmatrix.sync.aligned.m8n8.x2.shared.b16 {%0,%1}, [%2];"
                             : "=r"(bfrag[nf][ks][0]), "=r"(bfrag[nf][ks][1])
                             : "r"(addr));
            }
        }
        const int qc0   = (lane & 3) * 2;
        const int qbase = wid * 16;
        float thrv[2][2];
#pragma unroll
        for (int nf = 0; nf < 2; nf++)
#pragma unroll
            for (int par = 0; par < 2; par++)
                thrv[nf][par] = thr[qbase + nf * 8 + qc0 + par];
        MMA_BAR();                         // all bfrag reads done; stage reusable

        // prologue tile0: issue -> wait -> convert (per-thread chunk ownership)
        issue_tile(sb + SM_STAGE, corp, base, tid);
        asm volatile("cp.async.wait_group 0;\n");
#pragma unroll
        for (int j = 0; j < 8; j++) convert_chunk(sm, 0, j, tid);

        const int a_row_in = (lane & 7) + ((lane >> 3) & 1) * 8;
        const int a_col16  = (lane >> 4) * 16;
        const int mr0      = lane >> 2;

        for (int ti = 0; ti < TPB_M; ti++) {
            MMA_BAR();                    // publish A8[ti&1]

            const int  nxt     = ti + 1;
            const bool do_next = nxt < TPB_M;
            if (do_next) issue_tile(sb + SM_STAGE, corp, base + nxt, tid);

            const int abuf = ti & 1;
            const int tile_ibase = (base + ti) * TILE_M;
            const uint32_t a_base = sb + SM_A + abuf * A8_BUF;

#pragma unroll
            for (int mf = 0; mf < 8; mf++) {
                float acc[2][4];
#pragma unroll
                for (int nf = 0; nf < 2; nf++)
#pragma unroll
                    for (int r = 0; r < 4; r++) acc[nf][r] = 0.f;

#pragma unroll
                for (int ks = 0; ks < 4; ks++) {
                    uint32_t a[4];
                    uint32_t addr = a_base + (mf * 16 + a_row_in) * A8_STRIDE + ks * 32 + a_col16;
                    asm volatile("ldmatrix.sync.aligned.m8n8.x4.shared.b16 {%0,%1,%2,%3}, [%4];"
                                 : "=r"(a[0]), "=r"(a[1]), "=r"(a[2]), "=r"(a[3])
                                 : "r"(addr));
#pragma unroll
                    for (int nf = 0; nf < 2; nf++) {
                        asm volatile(
                            "mma.sync.aligned.m16n8k32.row.col.f32.e4m3.e4m3.f32 "
                            "{%0,%1,%2,%3}, {%4,%5,%6,%7}, {%8,%9}, {%0,%1,%2,%3};"
                            : "+f"(acc[nf][0]), "+f"(acc[nf][1]),
                              "+f"(acc[nf][2]), "+f"(acc[nf][3])
                            : "r"(a[0]), "r"(a[1]), "r"(a[2]), "r"(a[3]),
                              "r"(bfrag[nf][ks][0]), "r"(bfrag[nf][ks][1]));
                    }
                }

                if (mf == 4 && do_next) asm volatile("cp.async.wait_group 0;\n");
                if (mf >= 4 && do_next) {
                    convert_chunk(sm, nxt & 1, (mf - 4) * 2, tid);
                    convert_chunk(sm, nxt & 1, (mf - 4) * 2 + 1, tid);
                }

                float m00 = fmaxf(acc[0][0], acc[0][2]);
                float m01 = fmaxf(acc[0][1], acc[0][3]);
                float m10 = fmaxf(acc[1][0], acc[1][2]);
                float m11 = fmaxf(acc[1][1], acc[1][3]);
                bool hit = (m00 > thrv[0][0]) | (m01 > thrv[0][1])
                         | (m10 > thrv[1][0]) | (m11 > thrv[1][1]);
                if (hit) {
#pragma unroll
                    for (int nf = 0; nf < 2; nf++)
#pragma unroll
                        for (int r = 0; r < 4; r++) {
                            float v = acc[nf][r];
                            if (v > thrv[nf][r & 1]) {
                                int qc = qbase + nf * 8 + qc0 + (r & 1);
                                int item = tile_ibase + mf * 16 + mr0 + ((r >> 1) * 8);
                                int p = atomicAdd(&g_cnt[qc], 1);
                                if (p < CAP) g_cand_idx[(size_t)qc * CAP + p] = item;
                            }
                        }
                }
            }
        }
    } else {
        // =================== scalar HFMA2 path (warps 16-19) ===================
        const int sw = wid - 16;          // 0..3
        float thrmin[4];
#pragma unroll
        for (int p = 0; p < 4; p++) {
            float m = thr[p * 64];
            for (int qq = 1; qq < 64; qq++) m = fminf(m, thr[p * 64 + qq]);
            thrmin[p] = m;
        }
        const int sstart = SCAL_START + blockIdx.x * SCAL_CHUNK;
        int send = sstart + SCAL_CHUNK;
        if (send > NCORP) send = NCORP;

        for (int bb = sstart + sw * 32; bb < send; bb += 128) {
            const int item  = bb + lane;
            const bool valid = item < send;
            const float4* ip = (const float4*)(corp + (size_t)(valid ? item : 0) * D);

#pragma unroll
            for (int pass = 0; pass < 4; pass++) {
                half2 acc[32];
#pragma unroll
                for (int j = 0; j < 32; j++) acc[j] = __float2half2_rn(0.f);

                for (int k4 = 0; k4 < 32; k4++) {
                    float4 v = __ldg(&ip[k4]);
                    half2 a0 = __half2half2(__float2half_rn(v.x));
                    half2 a1 = __half2half2(__float2half_rn(v.y));
                    half2 a2 = __half2half2(__float2half_rn(v.z));
                    half2 a3 = __half2half2(__float2half_rn(v.w));
                    const half2* r0 = (const half2*)(sm + SM_QPK + (k4 * 4 + 0) * 512 + pass * 128);
                    const half2* r1 = (const half2*)(sm + SM_QPK + (k4 * 4 + 1) * 512 + pass * 128);
                    const half2* r2 = (const half2*)(sm + SM_QPK + (k4 * 4 + 2) * 512 + pass * 128);
                    const half2* r3 = (const half2*)(sm + SM_QPK + (k4 * 4 + 3) * 512 + pass * 128);
#pragma unroll
                    for (int j = 0; j < 32; j++) {
                        acc[j] = __hfma2(a0, r0[j], acc[j]);
                        acc[j] = __hfma2(a1, r1[j], acc[j]);
                        acc[j] = __hfma2(a2, r2[j], acc[j]);
                        acc[j] = __hfma2(a3, r3[j], acc[j]);
                    }
                }

                half2 m = acc[0];
#pragma unroll
                for (int j = 1; j < 32; j++) m = __hmax2(m, acc[j]);
                float mx = fmaxf(__low2float(m), __high2float(m));
                if (valid && mx > thrmin[pass]) {
#pragma unroll
                    for (int j = 0; j < 32; j++) {
                        float2 f = __half22float2(acc[j]);
                        int q0 = pass * 64 + 2 * j;
                        if (f.x > thr[q0]) {
                            int p = atomicAdd(&g_cnt[q0], 1);
                            if (p < CAP) g_cand_idx[(size_t)q0 * CAP + p] = item;
                        }
                        if (f.y > thr[q0 + 1]) {
                            int p = atomicAdd(&g_cnt[q0 + 1], 1);
                            if (p < CAP) g_cand_idx[(size_t)(q0 + 1) * CAP + p] = item;
                        }
                    }
                }
            }
        }
    }
}

// ---------------- K2: exact fp32 rescore + top-k + gather -------------------
__global__ __launch_bounds__(256) void rescore_topk_kernel(const float* __restrict__ qry,
                                                           const float* __restrict__ corp,
                                                           float* __restrict__ out) {
    __shared__ float qv[D];
    __shared__ unsigned int hist[NBINS];
    __shared__ float fs[FCAP];
    __shared__ int   fi[FCAP];
    __shared__ int   chosen[K_TOP];
    __shared__ int   s_cnt;
    __shared__ int   s_bin;

    const int q = blockIdx.x;
    const int tid = threadIdx.x;
    int n = g_cnt[q];
    if (n > CAP) n = CAP;

    if (tid < D) qv[tid] = qry[(size_t)q * D + tid];
    for (int i = tid; i < NBINS; i += blockDim.x) hist[i] = 0u;
    if (tid < K_TOP) chosen[tid] = 0;
    if (tid == 0) s_cnt = 0;
    __syncthreads();

    // exact fp32 rescore: SINGLE accumulator, strict sequential k-order (rel_err 0.0 path)
    for (int i = tid; i < n; i += blockDim.x) {
        int id = g_cand_idx[(size_t)q * CAP + i];
        const float4* cp = (const float4*)(corp + (size_t)id * D);
        float s = 0.f;
#pragma unroll
        for (int c = 0; c < D / 4; c++) {
            float4 v = cp[c];
            const float* qp = qv + c * 4;
            s = fmaf(v.x, qp[0], s);
            s = fmaf(v.y, qp[1], s);
            s = fmaf(v.z, qp[2], s);
            s = fmaf(v.w, qp[3], s);
        }
        g_cand_score[(size_t)q * CAP + i] = s;
        atomicAdd(&hist[fkey(s)], 1u);
    }
    __syncthreads();

    if (tid == 0) {
        unsigned int cum = 0;
        int b = NBINS - 1;
        for (; b > 0; b--) {
            cum += hist[b];
            if (cum >= K_TOP) break;
        }
        s_bin = b;
    }
    __syncthreads();

    const unsigned int sb2 = (unsigned int)s_bin;
    for (int i = tid; i < n; i += blockDim.x) {
        float s = g_cand_score[(size_t)q * CAP + i];
        if (fkey(s) >= sb2) {
            int p = atomicAdd(&s_cnt, 1);
            if (p < FCAP) {
                fs[p] = s;
                fi[p] = g_cand_idx[(size_t)q * CAP + i];
            }
        }
    }
    __syncthreads();

    int nf = s_cnt;
    if (nf > FCAP) nf = FCAP;

    // exact rank: (score desc, index asc) — matches jax.lax.top_k tie-break
    for (int i = tid; i < nf; i += blockDim.x) {
        float v = fs[i];
        int id = fi[i];
        int rank = 0;
        for (int j = 0; j < nf; j++) {
            float w = fs[j];
            rank += (w > v) || (w == v && fi[j] < id);
        }
        if (rank < K_TOP) {
            out[q * K_TOP + rank] = (float)id;
            chosen[rank] = id;
        }
    }
    __syncthreads();

    float* g = out + B * K_TOP;
    for (int r = tid / 32; r < K_TOP; r += blockDim.x / 32) {
        int id = chosen[r];
        const float4* src = (const float4*)(corp + (size_t)id * D);
        float4* dst = (float4*)(g + ((size_t)q * K_TOP + r) * D);
        int l = tid & 31;
        if (l < D / 4) dst[l] = src[l];
    }
}

// ---------------- launch ----------------
extern "C" void kernel_launch(void* const* d_in, const int* in_sizes, int n_in,
                              void* d_out, int out_size) {
    const float* qry = (const float*)d_in[0];
    const float* corp = (const float*)d_in[1];
    float* out = (float*)d_out;

    cudaFuncSetAttribute(gemm_filter_kernel,
                         cudaFuncAttributeMaxDynamicSharedMemorySize, SM_TOTAL);

    qprep_kernel<<<32, 256>>>(qry);
    gemm_filter_kernel<<<GRID_K1, NTHREADS, SM_TOTAL>>>(corp);
    rescore_topk_kernel<<<B, 256>>>(qry, corp, out);
}

// round 12
// speedup vs baseline: 2.3504x; 2.3504x over previous
#include <cuda_runtime.h>
#include <cuda_fp16.h>
#include <stdint.h>

#define B 256
#define D 128
#define NCORP 1000000
#define K_TOP 100
#define CAP 4096
#define NBINS 4096
#define FCAP 512
#define TILE_M 128
#define NTILE 7813
#define GRID_K1 148
#define TPB 53
#define THR_MULT 3.2f

// smem offsets
#define SM_A     0         // 2 x [128][136] half = 69,632
#define SM_STAGE 69632     // 65,536 (fp32 tile staging; Q halves at start)
#define SM_THR   135168    // 1,024
#define SM_TOTAL 136192

// ---------------- scratch (device globals; no allocations) ----------------
__device__ int    g_cnt[B];
__device__ float  g_thrf[B];
__device__ __half g_qh[B * D];                         // fp16 queries (64 KB)
__device__ int    g_cand_idx[(size_t)B * CAP];
__device__ float  g_cand_score[(size_t)B * CAP];

__device__ __forceinline__ unsigned int fkey(float f) {
    unsigned int u = __float_as_uint(f);
    u ^= (u & 0x80000000u) ? 0xFFFFFFFFu : 0x80000000u;
    return u >> 20;
}
__device__ __forceinline__ void cp_async16(uint32_t saddr, const void* g, int src_bytes) {
    asm volatile("cp.async.cg.shared.global [%0], [%1], 16, %2;\n"
                 :: "r"(saddr), "l"(g), "r"(src_bytes));
}
__device__ __forceinline__ uint32_t smem_u32(const void* p) {
    uint32_t a;
    asm("{ .reg .u64 t; cvta.to.shared.u64 t, %1; cvt.u32.u64 %0, t; }" : "=r"(a) : "l"(p));
    return a;
}

// ---------------- K0: Q fp32->fp16, thresholds, counter reset ----------------
__global__ __launch_bounds__(256) void qprep_kernel(const float* __restrict__ qry) {
    const int lane = threadIdx.x & 31;
    const int q = blockIdx.x * 8 + (threadIdx.x >> 5);
    float4 v = *(const float4*)(qry + (size_t)q * D + lane * 4);
    *(half2*)&g_qh[(size_t)q * D + lane * 4]     = __floats2half2_rn(v.x, v.y);
    *(half2*)&g_qh[(size_t)q * D + lane * 4 + 2] = __floats2half2_rn(v.z, v.w);
    float s = v.x * v.x + v.y * v.y + v.z * v.z + v.w * v.w;
#pragma unroll
    for (int o = 16; o > 0; o >>= 1) s += __shfl_xor_sync(0xFFFFFFFFu, s, o);
    if (lane == 0) {
        g_thrf[q] = THR_MULT * sqrtf(s);
        g_cnt[q] = 0;
    }
}

// ---------------- K1: persistent HMMA GEMM + filter, fp16 ACCUMULATORS -------
// Identical to the 414us round-7 kernel except the MMA uses f16 accumulation
// (testing the half-rate-for-f32-acc hypothesis on the legacy tensor pipe).
__device__ __forceinline__ void issue_tile(uint32_t sb, const float* __restrict__ corp,
                                           int tile, int tid) {
    const long ib = (long)tile * TILE_M;
#pragma unroll
    for (int j = 0; j < 8; j++) {
        int idx = tid + j * 512;          // 0..4095 16B chunks
        int row = idx >> 5;               // 32 chunks per 512B row
        int c16 = idx & 31;
        long item = ib + row;
        bool valid = item < NCORP;
        const float* g = valid ? corp + (size_t)item * D + c16 * 4 : corp;
        uint32_t sa = sb + SM_STAGE + row * 512 + c16 * 16;
        cp_async16(sa, g, valid ? 16 : 0);
    }
    asm volatile("cp.async.commit_group;\n");
}

__global__ __launch_bounds__(512, 1) void gemm_filter_kernel(const float* __restrict__ corp) {
    extern __shared__ __align__(1024) char sm[];
    const uint32_t sb = smem_u32(sm);
    __half (*A16)[136] = (__half(*)[136])(sm + SM_A);   // [2*128][136]
    float* thr = (float*)(sm + SM_THR);

    const int tid  = threadIdx.x;
    const int lane = tid & 31;
    const int wid  = tid >> 5;

    const int base = blockIdx.x * TPB;
    int nt = NTILE - base;
    if (nt > TPB) nt = TPB;
    if (nt < 0) nt = 0;

    // ---- stage Q (64 KB fp16) into SM_STAGE, layout [256 rows][128 halves] ----
#pragma unroll
    for (int j = 0; j < 8; j++) {
        int idx = tid + j * 512;
        int row = idx >> 4;
        int c16 = idx & 15;
        uint32_t sa = sb + SM_STAGE + row * 256 + c16 * 16;
        cp_async16(sa, g_qh + (size_t)row * D + c16 * 8, 16);
    }
    asm volatile("cp.async.commit_group;\n");
    if (tid < B) thr[tid] = g_thrf[tid];
    asm volatile("cp.async.wait_group 0;\n");
    __syncthreads();

    // ---- load B fragments once: warp's 16 queries ----
    const int b_l      = lane & 15;
    const int b_row_in = b_l & 7;
    const int b_col8   = (b_l >> 3) * 8;
    uint32_t bfrag[2][8][2];
#pragma unroll
    for (int nf = 0; nf < 2; nf++) {
#pragma unroll
        for (int ks = 0; ks < 8; ks++) {
            int qrow = wid * 16 + nf * 8 + b_row_in;
            uint32_t addr = sb + SM_STAGE + qrow * 256 + (ks * 16 + b_col8) * 2;
            asm volatile("ldmatrix.sync.aligned.m8n8.x2.shared.b16 {%0,%1}, [%2];"
                         : "=r"(bfrag[nf][ks][0]), "=r"(bfrag[nf][ks][1])
                         : "r"(addr));
        }
    }
    // per-thread thresholds
    const int qc0   = (lane & 3) * 2;
    const int qbase = wid * 16;
    float thrv[2][2];
#pragma unroll
    for (int nf = 0; nf < 2; nf++)
#pragma unroll
        for (int par = 0; par < 2; par++)
            thrv[nf][par] = thr[qbase + nf * 8 + qc0 + par];
    __syncthreads();                      // B frags read; stage free for corpus

    issue_tile(sb, corp, base, tid);      // prefetch first corpus tile

    const int a_row_in = (lane & 7) + ((lane >> 3) & 1) * 8;
    const int a_col8   = (lane >> 4) * 8;
    const int mr0      = lane >> 2;

    for (int ti = 0; ti < nt; ti++) {
        asm volatile("cp.async.wait_group 0;\n");
        __syncthreads();                  // stage ready; A16[ti&1] reads done

        // convert stage fp32 -> A16[ti&1] fp16
        const int abuf = ti & 1;
#pragma unroll
        for (int j = 0; j < 8; j++) {
            int idx = tid + j * 512;
            int row = idx >> 5;
            int c16 = idx & 31;
            float4 v = ((const float4*)(sm + SM_STAGE))[idx];
            __half* dst = &A16[abuf * 128 + row][c16 * 4];
            *(half2*)dst       = __floats2half2_rn(v.x, v.y);
            *(half2*)(dst + 2) = __floats2half2_rn(v.z, v.w);
        }
        __syncthreads();                  // A16 ready; stage consumed

        if (ti + 1 < nt) issue_tile(sb, corp, base + ti + 1, tid);

        const int tile_ibase = (base + ti) * TILE_M;

#pragma unroll
        for (int mf = 0; mf < 8; mf++) {
            // f16 accumulators: per nf, 2 regs = {half2(row mr0), half2(row mr0+8)}
            uint32_t hacc[2][2];
#pragma unroll
            for (int nf = 0; nf < 2; nf++) { hacc[nf][0] = 0u; hacc[nf][1] = 0u; }

#pragma unroll
            for (int ks = 0; ks < 8; ks++) {
                uint32_t a[4];
                const __half* p = &A16[abuf * 128 + mf * 16 + a_row_in][ks * 16 + a_col8];
                uint32_t addr = (uint32_t)__cvta_generic_to_shared(p);
                asm volatile("ldmatrix.sync.aligned.m8n8.x4.shared.b16 {%0,%1,%2,%3}, [%4];"
                             : "=r"(a[0]), "=r"(a[1]), "=r"(a[2]), "=r"(a[3])
                             : "r"(addr));
#pragma unroll
                for (int nf = 0; nf < 2; nf++) {
                    asm volatile(
                        "mma.sync.aligned.m16n8k16.row.col.f16.f16.f16.f16 "
                        "{%0,%1}, {%2,%3,%4,%5}, {%6,%7}, {%0,%1};"
                        : "+r"(hacc[nf][0]), "+r"(hacc[nf][1])
                        : "r"(a[0]), "r"(a[1]), "r"(a[2]), "r"(a[3]),
                          "r"(bfrag[nf][ks][0]), "r"(bfrag[nf][ks][1]));
                }
            }

            // filter: unpack half2 -> floats, identical compares to round 7
#pragma unroll
            for (int nf = 0; nf < 2; nf++) {
                float2 f0 = __half22float2(*(half2*)&hacc[nf][0]);   // row mr0
                float2 f1 = __half22float2(*(half2*)&hacc[nf][1]);   // row mr0+8
                float v4[4] = { f0.x, f0.y, f1.x, f1.y };
#pragma unroll
                for (int r = 0; r < 4; r++) {
                    float v = v4[r];
                    int   qc = qbase + nf * 8 + qc0 + (r & 1);
                    int item = tile_ibase + mf * 16 + mr0 + ((r >> 1) * 8);
                    if (v > thrv[nf][r & 1] && item < NCORP) {
                        int p = atomicAdd(&g_cnt[qc], 1);
                        if (p < CAP) g_cand_idx[(size_t)qc * CAP + p] = item;
                    }
                }
            }
        }
    }
}

// ---------------- K2: exact fp32 rescore + top-k + gather -------------------
__global__ __launch_bounds__(256) void rescore_topk_kernel(const float* __restrict__ qry,
                                                           const float* __restrict__ corp,
                                                           float* __restrict__ out) {
    __shared__ float qv[D];
    __shared__ unsigned int hist[NBINS];
    __shared__ float fs[FCAP];
    __shared__ int   fi[FCAP];
    __shared__ int   chosen[K_TOP];
    __shared__ int   s_cnt;
    __shared__ int   s_bin;

    const int q = blockIdx.x;
    const int tid = threadIdx.x;
    int n = g_cnt[q];
    if (n > CAP) n = CAP;

    if (tid < D) qv[tid] = qry[(size_t)q * D + tid];
    for (int i = tid; i < NBINS; i += blockDim.x) hist[i] = 0u;
    if (tid < K_TOP) chosen[tid] = 0;
    if (tid == 0) s_cnt = 0;
    __syncthreads();

    // exact fp32 rescore: SINGLE accumulator, strict sequential k-order (rel_err 0.0 path)
    for (int i = tid; i < n; i += blockDim.x) {
        int id = g_cand_idx[(size_t)q * CAP + i];
        const float4* cp = (const float4*)(corp + (size_t)id * D);
        float s = 0.f;
#pragma unroll
        for (int c = 0; c < D / 4; c++) {
            float4 v = cp[c];
            const float* qp = qv + c * 4;
            s = fmaf(v.x, qp[0], s);
            s = fmaf(v.y, qp[1], s);
            s = fmaf(v.z, qp[2], s);
            s = fmaf(v.w, qp[3], s);
        }
        g_cand_score[(size_t)q * CAP + i] = s;
        atomicAdd(&hist[fkey(s)], 1u);
    }
    __syncthreads();

    if (tid == 0) {
        unsigned int cum = 0;
        int b = NBINS - 1;
        for (; b > 0; b--) {
            cum += hist[b];
            if (cum >= K_TOP) break;
        }
        s_bin = b;
    }
    __syncthreads();

    const unsigned int sb2 = (unsigned int)s_bin;
    for (int i = tid; i < n; i += blockDim.x) {
        float s = g_cand_score[(size_t)q * CAP + i];
        if (fkey(s) >= sb2) {
            int p = atomicAdd(&s_cnt, 1);
            if (p < FCAP) {
                fs[p] = s;
                fi[p] = g_cand_idx[(size_t)q * CAP + i];
            }
        }
    }
    __syncthreads();

    int nf = s_cnt;
    if (nf > FCAP) nf = FCAP;

    // exact rank: (score desc, index asc) — matches jax.lax.top_k tie-break
    for (int i = tid; i < nf; i += blockDim.x) {
        float v = fs[i];
        int id = fi[i];
        int rank = 0;
        for (int j = 0; j < nf; j++) {
            float w = fs[j];
            rank += (w > v) || (w == v && fi[j] < id);
        }
        if (rank < K_TOP) {
            out[q * K_TOP + rank] = (float)id;
            chosen[rank] = id;
        }
    }
    __syncthreads();

    float* g = out + B * K_TOP;
    for (int r = tid / 32; r < K_TOP; r += blockDim.x / 32) {
        int id = chosen[r];
        const float4* src = (const float4*)(corp + (size_t)id * D);
        float4* dst = (float4*)(g + ((size_t)q * K_TOP + r) * D);
        int l = tid & 31;
        if (l < D / 4) dst[l] = src[l];
    }
}

// ---------------- launch ----------------
extern "C" void kernel_launch(void* const* d_in, const int* in_sizes, int n_in,
                              void* d_out, int out_size) {
    const float* qry = (const float*)d_in[0];
    const float* corp = (const float*)d_in[1];
    float* out = (float*)d_out;

    cudaFuncSetAttribute(gemm_filter_kernel,
                         cudaFuncAttributeMaxDynamicSharedMemorySize, SM_TOTAL);

    qprep_kernel<<<32, 256>>>(qry);
    gemm_filter_kernel<<<GRID_K1, 512, SM_TOTAL>>>(corp);
    rescore_topk_kernel<<<B, 256>>>(qry, corp, out);
}